// round 16
// baseline (speedup 1.0000x reference)
#include <cuda_runtime.h>
#include <cuda_bf16.h>
#include <cstdint>

#define B_ 8
#define T_ 2048
#define H_ 1024
#define P_ 64
#define BT_ (B_ * T_)

// Scratch (no cudaMalloc allowed)
__device__ float g_q[BT_ * P_];
__device__ float g_k[BT_ * P_];
__device__ float g_v[BT_ * P_];
__device__ float g_att[BT_ * P_];
// QKV weights transposed to [n][k] (n=192, k=1024), split bf16 hi/lo
__device__ __align__(16) __nv_bfloat16 g_wt_hi[192 * 1024];
__device__ __align__(16) __nv_bfloat16 g_wt_lo[192 * 1024];
// Wo in mma B-fragment layout, hi+lo MERGED: [n8-tile(128)][k16(4)][lane(32)]
// uint4 = {h01, h89, l01, l89}: .x/.y = hi bf16x2 pair (k=2t,2t+1 / +8,+9),
// .z/.w = lo residual pair, at n = tile*8 + lane/4, k-pair = 2*(lane%4)
__device__ __align__(16) uint4 g_wo_f[128 * 4 * 32];

// ---------------------------------------------------------------------------
// Base-ISA tensor helpers (sm_80+; compile at plain sm_103)
// ---------------------------------------------------------------------------
__device__ __forceinline__ uint32_t smem_u32(const void* p) {
    uint32_t a;
    asm("{ .reg .u64 t; cvta.to.shared.u64 t, %1; cvt.u32.u64 %0, t; }"
        : "=r"(a) : "l"(p));
    return a;
}

__device__ __forceinline__ void ldsm4(uint32_t* r, uint32_t addr) {
    asm volatile("ldmatrix.sync.aligned.m8n8.x4.shared.b16 {%0,%1,%2,%3}, [%4];"
                 : "=r"(r[0]), "=r"(r[1]), "=r"(r[2]), "=r"(r[3]) : "r"(addr));
}

__device__ __forceinline__ void mma16816(float* d, const uint32_t* a,
                                         uint32_t b0, uint32_t b1) {
    asm volatile(
        "mma.sync.aligned.m16n8k16.row.col.f32.bf16.bf16.f32 "
        "{%0,%1,%2,%3}, {%4,%5,%6,%7}, {%8,%9}, {%0,%1,%2,%3};"
        : "+f"(d[0]), "+f"(d[1]), "+f"(d[2]), "+f"(d[3])
        : "r"(a[0]), "r"(a[1]), "r"(a[2]), "r"(a[3]), "r"(b0), "r"(b1));
}

__device__ __forceinline__ uint32_t b2u(__nv_bfloat162 v) {
    union { __nv_bfloat162 b; uint32_t u; } c;
    c.b = v;
    return c.u;
}

// Split 8 fp32 into bf16 hi (uint4) and residual lo (uint4)
__device__ __forceinline__ void split8(float4 a, float4 b, uint4& hi, uint4& lo) {
    __nv_bfloat162 h01 = __floats2bfloat162_rn(a.x, a.y);
    __nv_bfloat162 h23 = __floats2bfloat162_rn(a.z, a.w);
    __nv_bfloat162 h45 = __floats2bfloat162_rn(b.x, b.y);
    __nv_bfloat162 h67 = __floats2bfloat162_rn(b.z, b.w);
    __nv_bfloat162 l01 = __floats2bfloat162_rn(a.x - __low2float(h01), a.y - __high2float(h01));
    __nv_bfloat162 l23 = __floats2bfloat162_rn(a.z - __low2float(h23), a.w - __high2float(h23));
    __nv_bfloat162 l45 = __floats2bfloat162_rn(b.x - __low2float(h45), b.y - __high2float(h45));
    __nv_bfloat162 l67 = __floats2bfloat162_rn(b.z - __low2float(h67), b.w - __high2float(h67));
    hi = make_uint4(b2u(h01), b2u(h23), b2u(h45), b2u(h67));
    lo = make_uint4(b2u(l01), b2u(l23), b2u(l45), b2u(l67));
}

// Split 4 fp32 into bf16 hi (uint2) and residual lo (uint2)
__device__ __forceinline__ void split4(float4 v, uint2& hi, uint2& lo) {
    __nv_bfloat162 h01 = __floats2bfloat162_rn(v.x, v.y);
    __nv_bfloat162 h23 = __floats2bfloat162_rn(v.z, v.w);
    __nv_bfloat162 l01 = __floats2bfloat162_rn(v.x - __low2float(h01), v.y - __high2float(h01));
    __nv_bfloat162 l23 = __floats2bfloat162_rn(v.z - __low2float(h23), v.w - __high2float(h23));
    hi = make_uint2(b2u(h01), b2u(h23));
    lo = make_uint2(b2u(l01), b2u(l23));
}

// ---------------------------------------------------------------------------
// Prep: blocks 0-191 transpose+split QKV weights; blocks 192-255 build the
// merged Wo B-fragment array (16384 lanes, one uint4 per thread).
// ---------------------------------------------------------------------------
__global__ void prep_all(const float* __restrict__ Wq, const float* __restrict__ Wk,
                         const float* __restrict__ Wv, const float* __restrict__ Wo) {
    int bid = blockIdx.x;
    if (bid < 192) {
        int n = bid;
        const float* W = (n < 64) ? Wq : ((n < 128) ? Wk : Wv);
        int col = n & 63;
        for (int k = threadIdx.x; k < H_; k += 256) {
            float w = W[(size_t)k * P_ + col];
            __nv_bfloat16 h = __float2bfloat16_rn(w);
            g_wt_hi[(size_t)n * H_ + k] = h;
            g_wt_lo[(size_t)n * H_ + k] = __float2bfloat16_rn(w - __bfloat162float(h));
        }
    } else {
        int idx = (bid - 192) * 256 + threadIdx.x;   // 0..16383
        int lane = idx & 31;
        int ks   = (idx >> 5) & 3;
        int g8   = idx >> 7;                          // n8-tile 0..127
        int n = g8 * 8 + (lane >> 2);                 // 0..1023
        int k = ks * 16 + (lane & 3) * 2;             // 0..62
        float w0 = Wo[(size_t)(k + 0) * H_ + n];
        float w1 = Wo[(size_t)(k + 1) * H_ + n];
        float w8 = Wo[(size_t)(k + 8) * H_ + n];
        float w9 = Wo[(size_t)(k + 9) * H_ + n];
        __nv_bfloat162 h01 = __floats2bfloat162_rn(w0, w1);
        __nv_bfloat162 h89 = __floats2bfloat162_rn(w8, w9);
        __nv_bfloat162 l01 = __floats2bfloat162_rn(w0 - __low2float(h01),
                                                   w1 - __high2float(h01));
        __nv_bfloat162 l89 = __floats2bfloat162_rn(w8 - __low2float(h89),
                                                   w9 - __high2float(h89));
        g_wo_f[idx] = make_uint4(b2u(h01), b2u(h89), b2u(l01), b2u(l89));
    }
}

// ---------------------------------------------------------------------------
// Kernel 1: fused QKV projection via mma.sync (unchanged from R11)
// ---------------------------------------------------------------------------
#define QKV_STAGE 51200
#define QKV_AH 0
#define QKV_AL 10240
#define QKV_BH 20480
#define QKV_BL 35840
#define QKV_SMEM (1024 + 2 * QKV_STAGE)   // 103424

__global__ __launch_bounds__(256) void qkv_mma(
    const float* __restrict__ X,
    const float* __restrict__ bq, const float* __restrict__ bk,
    const float* __restrict__ bv)
{
    extern __shared__ char smem[];
    const uint32_t sb = smem_u32(smem);
    const int tid = threadIdx.x, lane = tid & 31, wid = tid >> 5;
    const int wm = wid >> 2, wn = wid & 3;
    const int m0 = blockIdx.x * 128;

    float* bias_s = (float*)smem;
    if (tid < 192)
        bias_s[tid] = (tid < 64) ? bq[tid] : ((tid < 128) ? bk[tid - 64] : bv[tid - 128]);

    const int a_row = tid >> 1;
    const int a_seg = (tid & 1) * 16;
    const float* Xrow = X + (size_t)(m0 + a_row) * H_ + a_seg;

    const uint32_t a_off = (uint32_t)((wm * 64 + (lane & 15)) * 80 + (lane & 16));
    const uint32_t b_off = (uint32_t)((wn * 48 + (lane & 7) + ((lane & 16) >> 1)) * 80
                                      + ((lane & 8) << 1));

    float4 ar0, ar1, ar2, ar3;
    uint4 brh[3], brl[3];

    float acc[4][6][4];
#pragma unroll
    for (int i = 0; i < 4; i++)
#pragma unroll
        for (int j = 0; j < 6; j++)
#pragma unroll
            for (int c = 0; c < 4; c++) acc[i][j][c] = 0.f;

#define QKV_LDG(c) do {                                                          \
    int k0 = (c) * 32;                                                           \
    ar0 = *(const float4*)(Xrow + k0);                                           \
    ar1 = *(const float4*)(Xrow + k0 + 4);                                       \
    ar2 = *(const float4*)(Xrow + k0 + 8);                                       \
    ar3 = *(const float4*)(Xrow + k0 + 12);                                      \
    _Pragma("unroll")                                                            \
    for (int i = 0; i < 3; i++) {                                                \
        int idx = tid + i * 256; int n = idx >> 2, sg = idx & 3;                 \
        brh[i] = *(const uint4*)(g_wt_hi + (size_t)n * H_ + k0 + sg * 8);        \
        brl[i] = *(const uint4*)(g_wt_lo + (size_t)n * H_ + k0 + sg * 8);        \
    } } while (0)

#define QKV_STS(s) do {                                                          \
    char* bp = smem + 1024 + (s) * QKV_STAGE;                                    \
    uint4 hi0, lo0, hi1, lo1;                                                    \
    split8(ar0, ar1, hi0, lo0);                                                  \
    split8(ar2, ar3, hi1, lo1);                                                  \
    *(uint4*)(bp + QKV_AH + a_row * 80 + a_seg * 2)      = hi0;                  \
    *(uint4*)(bp + QKV_AH + a_row * 80 + a_seg * 2 + 16) = hi1;                  \
    *(uint4*)(bp + QKV_AL + a_row * 80 + a_seg * 2)      = lo0;                  \
    *(uint4*)(bp + QKV_AL + a_row * 80 + a_seg * 2 + 16) = lo1;                  \
    _Pragma("unroll")                                                            \
    for (int i = 0; i < 3; i++) {                                                \
        int idx = tid + i * 256; int n = idx >> 2, sg = idx & 3;                 \
        *(uint4*)(bp + QKV_BH + n * 80 + sg * 16) = brh[i];                      \
        *(uint4*)(bp + QKV_BL + n * 80 + sg * 16) = brl[i];                      \
    } } while (0)

    QKV_LDG(0);
    QKV_STS(0);
    __syncthreads();

    for (int c = 0; c < 32; ++c) {
        const int s = c & 1;
        if (c < 31) QKV_LDG(c + 1);
        const uint32_t base = sb + 1024 + s * QKV_STAGE;
#pragma unroll
        for (int ks = 0; ks < 2; ++ks) {
            uint32_t ah[4][4], al[4][4];
#pragma unroll
            for (int mt = 0; mt < 4; mt++) {
                ldsm4(ah[mt], base + QKV_AH + a_off + mt * 1280 + ks * 32);
                ldsm4(al[mt], base + QKV_AL + a_off + mt * 1280 + ks * 32);
            }
#pragma unroll
            for (int np = 0; np < 3; ++np) {
                uint32_t bh[4], bl[4];
                ldsm4(bh, base + QKV_BH + b_off + np * 1280 + ks * 32);
                ldsm4(bl, base + QKV_BL + b_off + np * 1280 + ks * 32);
#pragma unroll
                for (int hh = 0; hh < 2; ++hh) {
                    const int nt = np * 2 + hh;
#pragma unroll
                    for (int mt = 0; mt < 4; mt++) {
                        mma16816(acc[mt][nt], ah[mt], bh[2 * hh], bh[2 * hh + 1]);
                        mma16816(acc[mt][nt], ah[mt], bl[2 * hh], bl[2 * hh + 1]);
                        mma16816(acc[mt][nt], al[mt], bh[2 * hh], bh[2 * hh + 1]);
                    }
                }
            }
        }
        if (c < 31) { QKV_STS(s ^ 1); __syncthreads(); }
    }

    const int r0 = m0 + wm * 64 + (lane >> 2);
#pragma unroll
    for (int mt = 0; mt < 4; ++mt)
#pragma unroll
        for (int nt = 0; nt < 6; ++nt) {
            int n = wn * 48 + nt * 8 + (lane & 3) * 2;
            float* out = (n < 64) ? g_q : ((n < 128) ? g_k : g_v);
            int cn = n & 63;
            int row = r0 + mt * 16;
            float b0 = bias_s[n], b1 = bias_s[n + 1];
            *(float2*)(out + (size_t)row * P_ + cn) =
                make_float2(acc[mt][nt][0] + b0, acc[mt][nt][1] + b1);
            *(float2*)(out + (size_t)(row + 8) * P_ + cn) =
                make_float2(acc[mt][nt][2] + b0, acc[mt][nt][3] + b1);
        }
}

// ---------------------------------------------------------------------------
// Kernel 2: banded attention via mma.sync — smem lifetime overlap (R13, 2 CTA/SM)
// ---------------------------------------------------------------------------
#define AT_KH   0
#define AT_KL   27648
#define AT_VH   0
#define AT_VL   25600
#define AT_QH   55296
#define AT_QL   64512
#define AT_PART 55296
#define AT_BIAS 73728
#define AT_MAX  74496
#define AT_SUM  75008
#define AT_SMEM 75520

__global__ __launch_bounds__(256, 2) void attn_mma(const float* __restrict__ biasg)
{
    extern __shared__ char smem[];
    const uint32_t sb = smem_u32(smem);
    const int tid = threadIdx.x, lane = tid & 31, w = tid >> 5;
    const int h = w >> 2, rb = w & 3;
    const int b  = blockIdx.x >> 5;
    const int t0 = (blockIdx.x & 31) << 6;

    const float* Kg = g_k + (size_t)b * T_ * P_;
    const float* Vg = g_v + (size_t)b * T_ * P_;
    const float* Qg = g_q + ((size_t)b * T_ + t0) * P_;

    for (int idx = tid; idx < 192 * 16; idx += 256) {
        int j = idx >> 4, d4 = (idx & 15) << 2;
        int jg = t0 - 64 + j;
        float4 kv = make_float4(0.f, 0.f, 0.f, 0.f);
        if (jg >= 0 && jg < T_)
            kv = *(const float4*)(Kg + (size_t)jg * P_ + d4);
        uint2 khi, klo;
        split4(kv, khi, klo);
        *(uint2*)(smem + AT_KH + j * 144 + d4 * 2) = khi;
        *(uint2*)(smem + AT_KL + j * 144 + d4 * 2) = klo;
    }
    for (int idx = tid; idx < 64 * 16; idx += 256) {
        int r = idx >> 4, d4 = (idx & 15) << 2;
        float4 qv = *(const float4*)(Qg + (size_t)r * P_ + d4);
        uint2 qhi, qlo;
        split4(qv, qhi, qlo);
        *(uint2*)(smem + AT_QH + r * 144 + d4 * 2) = qhi;
        *(uint2*)(smem + AT_QL + r * 144 + d4 * 2) = qlo;
    }
    float* bias_s = (float*)(smem + AT_BIAS);
    for (int d = tid; d < 192; d += 256)
        bias_s[d] = (d <= 128) ? biasg[1984 + d] : 0.f;
    __syncthreads();

    const uint32_t a_off = (uint32_t)((rb * 16 + (lane & 15)) * 144 + (lane & 16));
    const uint32_t b_off = (uint32_t)(((lane & 7) + ((lane & 16) >> 1)) * 144
                                      + ((lane & 8) << 1));
    float acc[12][4];
#pragma unroll
    for (int nt = 0; nt < 12; nt++)
#pragma unroll
        for (int c = 0; c < 4; c++) acc[nt][c] = 0.f;

#pragma unroll
    for (int ks = 0; ks < 4; ++ks) {
        uint32_t qh[4], ql[4];
        ldsm4(qh, sb + AT_QH + a_off + ks * 32);
        ldsm4(ql, sb + AT_QL + a_off + ks * 32);
#pragma unroll
        for (int np = 0; np < 6; ++np) {
            uint32_t kb = sb + b_off + (uint32_t)((h * 96 + np * 16) * 144) + ks * 32;
            uint32_t kh4[4], kl4[4];
            ldsm4(kh4, kb + AT_KH);
            ldsm4(kl4, kb + AT_KL);
#pragma unroll
            for (int hh = 0; hh < 2; ++hh) {
                const int nt = np * 2 + hh;
                mma16816(acc[nt], qh, kh4[2 * hh], kh4[2 * hh + 1]);
                mma16816(acc[nt], qh, kl4[2 * hh], kl4[2 * hh + 1]);
                mma16816(acc[nt], ql, kh4[2 * hh], kh4[2 * hh + 1]);
            }
        }
    }

    const int r1 = rb * 16 + (lane >> 2);
    const int r2 = r1 + 8;
    float* smax = (float*)(smem + AT_MAX);
    float* ssum = (float*)(smem + AT_SUM);

    float m1 = -1e30f, m2v = -1e30f;
#pragma unroll
    for (int nt = 0; nt < 12; nt++) {
        int cbase = h * 96 + nt * 8 + 2 * (lane & 3);
#pragma unroll
        for (int e = 0; e < 2; e++) {
            int c = cbase + e;
            int jg = t0 - 64 + c;
            bool jv = (jg >= 0 && jg < T_);
            int rel1 = c - r1;
            bool v1 = jv && rel1 >= 0 && rel1 <= 128;
            float s1v = v1 ? fmaf(acc[nt][e], 0.125f, bias_s[rel1]) : -1e30f;
            acc[nt][e] = s1v;
            m1 = fmaxf(m1, s1v);
            int rel2 = c - r2;
            bool v2 = jv && rel2 >= 0 && rel2 <= 128;
            float s2v = v2 ? fmaf(acc[nt][2 + e], 0.125f, bias_s[rel2]) : -1e30f;
            acc[nt][2 + e] = s2v;
            m2v = fmaxf(m2v, s2v);
        }
    }
    m1  = fmaxf(m1,  __shfl_xor_sync(0xffffffffu, m1, 1));
    m1  = fmaxf(m1,  __shfl_xor_sync(0xffffffffu, m1, 2));
    m2v = fmaxf(m2v, __shfl_xor_sync(0xffffffffu, m2v, 1));
    m2v = fmaxf(m2v, __shfl_xor_sync(0xffffffffu, m2v, 2));
    if ((lane & 3) == 0) {
        smax[h * 64 + r1] = m1;
        smax[h * 64 + r2] = m2v;
    }
    __syncthreads();
    const float gm1 = fmaxf(smax[r1], smax[64 + r1]);
    const float gm2 = fmaxf(smax[r2], smax[64 + r2]);

    float su1 = 0.f, su2 = 0.f;
#pragma unroll
    for (int nt = 0; nt < 12; nt++) {
#pragma unroll
        for (int e = 0; e < 2; e++) {
            float p1 = __expf(acc[nt][e] - gm1);
            float p2 = __expf(acc[nt][2 + e] - gm2);
            acc[nt][e] = p1;
            acc[nt][2 + e] = p2;
            su1 += p1;
            su2 += p2;
        }
    }
    su1 += __shfl_xor_sync(0xffffffffu, su1, 1);
    su1 += __shfl_xor_sync(0xffffffffu, su1, 2);
    su2 += __shfl_xor_sync(0xffffffffu, su2, 1);
    su2 += __shfl_xor_sync(0xffffffffu, su2, 2);
    if ((lane & 3) == 0) {
        ssum[h * 64 + r1] = su1;
        ssum[h * 64 + r2] = su2;
    }

    // Stage transposed V into the retired K region
    for (int idx = tid; idx < 192 * 16; idx += 256) {
        int j = idx >> 4, d4 = (idx & 15) << 2;
        int jg = t0 - 64 + j;
        float4 vv = make_float4(0.f, 0.f, 0.f, 0.f);
        if (jg >= 0 && jg < T_)
            vv = *(const float4*)(Vg + (size_t)jg * P_ + d4);
        float vals[4] = {vv.x, vv.y, vv.z, vv.w};
#pragma unroll
        for (int i = 0; i < 4; i++) {
            int d = d4 + i;
            __nv_bfloat16 vh = __float2bfloat16_rn(vals[i]);
            *(__nv_bfloat16*)(smem + AT_VH + d * 400 + j * 2) = vh;
            *(__nv_bfloat16*)(smem + AT_VL + d * 400 + j * 2) =
                __float2bfloat16_rn(vals[i] - __bfloat162float(vh));
        }
    }

    uint32_t ph[24], pl[24];
#pragma unroll
    for (int nt = 0; nt < 12; nt++) {
        __nv_bfloat162 h01 = __floats2bfloat162_rn(acc[nt][0], acc[nt][1]);
        __nv_bfloat162 h23 = __floats2bfloat162_rn(acc[nt][2], acc[nt][3]);
        ph[2 * nt]     = b2u(h01);
        ph[2 * nt + 1] = b2u(h23);
        pl[2 * nt]     = b2u(__floats2bfloat162_rn(acc[nt][0] - __low2float(h01),
                                                   acc[nt][1] - __high2float(h01)));
        pl[2 * nt + 1] = b2u(__floats2bfloat162_rn(acc[nt][2] - __low2float(h23),
                                                   acc[nt][3] - __high2float(h23)));
    }
    __syncthreads();

    const uint32_t vt_off = (uint32_t)(((lane & 7) + ((lane & 16) >> 1)) * 400
                                       + ((lane & 8) << 1) + h * 192);
    float oacc[8][4];
#pragma unroll
    for (int nt = 0; nt < 8; nt++)
#pragma unroll
        for (int c = 0; c < 4; c++) oacc[nt][c] = 0.f;

#pragma unroll
    for (int kk = 0; kk < 6; ++kk) {
        const uint32_t* aph = ph + kk * 4;
        const uint32_t* apl = pl + kk * 4;
#pragma unroll
        for (int nv = 0; nv < 4; ++nv) {
            uint32_t vb = sb + vt_off + (uint32_t)(nv * 6400) + kk * 32;
            uint32_t vh4[4], vl4[4];
            ldsm4(vh4, vb + AT_VH);
            ldsm4(vl4, vb + AT_VL);
#pragma unroll
            for (int hh = 0; hh < 2; ++hh) {
                const int nt = nv * 2 + hh;
                mma16816(oacc[nt], aph, vh4[2 * hh], vh4[2 * hh + 1]);
                mma16816(oacc[nt], aph, vl4[2 * hh], vl4[2 * hh + 1]);
                mma16816(oacc[nt], apl, vh4[2 * hh], vh4[2 * hh + 1]);
            }
        }
    }

    float* part = (float*)(smem + AT_PART);
    if (h == 1) {
#pragma unroll
        for (int nt = 0; nt < 8; nt++) {
            int col = nt * 8 + 2 * (lane & 3);
            *(float2*)(part + r1 * 66 + col) = make_float2(oacc[nt][0], oacc[nt][1]);
            *(float2*)(part + r2 * 66 + col) = make_float2(oacc[nt][2], oacc[nt][3]);
        }
    }
    __syncthreads();
    if (h == 0) {
        const float inv1 = 1.f / (ssum[r1] + ssum[64 + r1]);
        const float inv2 = 1.f / (ssum[r2] + ssum[64 + r2]);
        float* O1 = g_att + ((size_t)b * T_ + t0 + r1) * P_;
        float* O2 = g_att + ((size_t)b * T_ + t0 + r2) * P_;
#pragma unroll
        for (int nt = 0; nt < 8; nt++) {
            int col = nt * 8 + 2 * (lane & 3);
            float2 p1 = *(float2*)(part + r1 * 66 + col);
            float2 p2 = *(float2*)(part + r2 * 66 + col);
            *(float2*)(O1 + col) = make_float2((oacc[nt][0] + p1.x) * inv1,
                                               (oacc[nt][1] + p1.y) * inv1);
            *(float2*)(O2 + col) = make_float2((oacc[nt][2] + p2.x) * inv2,
                                               (oacc[nt][3] + p2.y) * inv2);
        }
    }
}

// ---------------------------------------------------------------------------
// Kernel 3: output projection — merged uint4 B fragments from gmem, batched
// per-k-step loads (MLP=4 LDG.128).  BM=64, grid 256, warps 4m x 2n.
// smem: A hi/lo only (18.4 KB) -> 2 CTA/SM.
// ---------------------------------------------------------------------------
#define OP3_AH 0
#define OP3_AL 9216
#define OP3_SMEM 18432

__global__ __launch_bounds__(256, 2) void outproj_mma(
    const float* __restrict__ bo, float* __restrict__ O)
{
    extern __shared__ char smem[];
    const uint32_t sb = smem_u32(smem);
    const int tid = threadIdx.x, lane = tid & 31, wid = tid >> 5;
    const int wm = wid >> 1, wn = wid & 1;
    const int m0 = blockIdx.x * 64;

    // Stage A (g_att 64x64 fp32 -> bf16 hi/lo, stride 144B)
    {
        int row = tid >> 2, ks = (tid & 3) * 16;
        const float* ap = g_att + (size_t)(m0 + row) * P_ + ks;
        float4 f0 = *(const float4*)(ap + 0);
        float4 f1 = *(const float4*)(ap + 4);
        float4 f2 = *(const float4*)(ap + 8);
        float4 f3 = *(const float4*)(ap + 12);
        uint4 hi0, lo0, hi1, lo1;
        split8(f0, f1, hi0, lo0);
        split8(f2, f3, hi1, lo1);
        *(uint4*)(smem + OP3_AH + row * 144 + ks * 2)      = hi0;
        *(uint4*)(smem + OP3_AH + row * 144 + ks * 2 + 16) = hi1;
        *(uint4*)(smem + OP3_AL + row * 144 + ks * 2)      = lo0;
        *(uint4*)(smem + OP3_AL + row * 144 + ks * 2 + 16) = lo1;
    }
    __syncthreads();

    // Hoist A fragments: warp covers rows wm*16..wm*16+15, all 4 k16 tiles
    const uint32_t a_off = (uint32_t)((wm * 16 + (lane & 15)) * 144 + (lane & 16));
    uint32_t ahf[4][4], alf[4][4];
#pragma unroll
    for (int ks = 0; ks < 4; ++ks) {
        ldsm4(ahf[ks], sb + OP3_AH + a_off + ks * 32);
        ldsm4(alf[ks], sb + OP3_AL + a_off + ks * 32);
    }

    const int r0 = m0 + wm * 16 + (lane >> 2);

    // Loop over 16 n-tiles of 64; warp handles n8-tiles g8 = nb*8 + wn*4 + j
    for (int nb = 0; nb < 16; ++nb) {
        float acc[4][4];
#pragma unroll
        for (int j = 0; j < 4; j++)
#pragma unroll
            for (int c = 0; c < 4; c++) acc[j][c] = 0.f;

        const int g8base = nb * 8 + wn * 4;
#pragma unroll
        for (int ks = 0; ks < 4; ++ks) {
            uint4 bf[4];
#pragma unroll
            for (int j = 0; j < 4; ++j)
                bf[j] = __ldg(&g_wo_f[((g8base + j) * 4 + ks) * 32 + lane]);
#pragma unroll
            for (int j = 0; j < 4; ++j) {
                mma16816(acc[j], ahf[ks], bf[j].x, bf[j].y);
                mma16816(acc[j], ahf[ks], bf[j].z, bf[j].w);
                mma16816(acc[j], alf[ks], bf[j].x, bf[j].y);
            }
        }

#pragma unroll
        for (int j = 0; j < 4; ++j) {
            int n = (g8base + j) * 8 + (lane & 3) * 2;
            float b0 = __ldg(bo + n), b1 = __ldg(bo + n + 1);
            *(float2*)(O + (size_t)r0 * H_ + n) =
                make_float2(acc[j][0] + b0, acc[j][1] + b1);
            *(float2*)(O + (size_t)(r0 + 8) * H_ + n) =
                make_float2(acc[j][2] + b0, acc[j][3] + b1);
        }
    }
}

// ---------------------------------------------------------------------------
// Launch
// ---------------------------------------------------------------------------
extern "C" void kernel_launch(void* const* d_in, const int* in_sizes, int n_in,
                              void* d_out, int out_size)
{
    (void)in_sizes; (void)n_in; (void)out_size;
    const float* X    = (const float*)d_in[0];
    const float* Wq   = (const float*)d_in[2];
    const float* bq   = (const float*)d_in[3];
    const float* Wk   = (const float*)d_in[4];
    const float* bk   = (const float*)d_in[5];
    const float* Wv   = (const float*)d_in[6];
    const float* bv   = (const float*)d_in[7];
    const float* Wo   = (const float*)d_in[8];
    const float* bo   = (const float*)d_in[9];
    const float* bias = (const float*)d_in[10];
    float* O = (float*)d_out;

    prep_all<<<256, 256>>>(Wq, Wk, Wv, Wo);

    cudaFuncSetAttribute(qkv_mma, cudaFuncAttributeMaxDynamicSharedMemorySize,
                         QKV_SMEM);
    qkv_mma<<<128, 256, QKV_SMEM>>>(X, bq, bk, bv);

    cudaFuncSetAttribute(attn_mma, cudaFuncAttributeMaxDynamicSharedMemorySize,
                         AT_SMEM);
    attn_mma<<<256, 256, AT_SMEM>>>(bias);

    cudaFuncSetAttribute(outproj_mma, cudaFuncAttributeMaxDynamicSharedMemorySize,
                         OP3_SMEM);
    outproj_mma<<<256, 256, OP3_SMEM>>>(bo, O);
}